// round 11
// baseline (speedup 1.0000x reference)
#include <cuda_runtime.h>
#include <math.h>

#define B_   64
#define D_   4096
#define HKV_ 8
#define G_   4
#define DH_  128
#define W_   2048
#define STAGES 3
#define SK   16                    // split-K factor
#define QKV_N (D_ + 2 * HKV_ * DH_)   // 6144 concat output cols (q | knew | vnew)

// ---------------- scratch (device globals; no allocations allowed) ----------------
__device__ float g_q    [B_ * D_];             // q (RoPE'd)
__device__ float g_knew [B_ * HKV_ * DH_];     // new k (RoPE'd)
__device__ float g_vnew [B_ * HKV_ * DH_];     // new v
__device__ float g_attn [B_ * D_];             // attention output
__device__ float g_oproj[B_ * D_];             // attn @ Wo^T
__device__ float g_part [SK * B_ * QKV_N];     // split-K partials (reused by all GEMMs)

// ================= tf32 tensor-core GEMM machinery ============
// 256 threads (8 warps), block tile 64(M) x 32(N), k-tile 32, 3-stage cp.async.
// warp grid: 4 (M) x 2 (N); warp tile 16x16 = 2x mma.m16n8k8.
// fp32 bits are fed RAW to the tf32 MMA (HW ignores mantissa[12:0]) — no cvt.

__device__ __forceinline__ void mma_tf32(float& c0, float& c1, float& c2, float& c3,
                                         unsigned a0, unsigned a1, unsigned a2, unsigned a3,
                                         unsigned b0, unsigned b1) {
    asm volatile("mma.sync.aligned.m16n8k8.row.col.f32.tf32.tf32.f32 "
                 "{%0,%1,%2,%3}, {%4,%5,%6,%7}, {%8,%9}, {%0,%1,%2,%3};"
                 : "+f"(c0), "+f"(c1), "+f"(c2), "+f"(c3)
                 : "r"(a0), "r"(a1), "r"(a2), "r"(a3), "r"(b0), "r"(b1));
}

#define CP16(dst_smem_u32, src_ptr) \
    asm volatile("cp.async.cg.shared.global [%0], [%1], 16;" :: "r"(dst_smem_u32), "l"(src_ptr))

__device__ __forceinline__ void load_tile(float As[STAGES][64][36], float Bs[STAGES][32][36],
                                          int buf,
                                          const float* __restrict__ Atile, int lda,
                                          const float* __restrict__ Wtile, int ldw, int tid)
{
    #pragma unroll
    for (int j = 0; j < 2; j++) {
        int f = tid + j * 256;
        int row = f >> 3, c4 = f & 7;
        unsigned dst = (unsigned)__cvta_generic_to_shared(&As[buf][row][c4 * 4]);
        CP16(dst, Atile + (size_t)row * lda + c4 * 4);
    }
    {
        int row = tid >> 3, c4 = tid & 7;
        unsigned dst = (unsigned)__cvta_generic_to_shared(&Bs[buf][row][c4 * 4]);
        CP16(dst, Wtile + (size_t)row * ldw + c4 * 4);
    }
    asm volatile("cp.async.commit_group;");
}

__device__ __forceinline__ void compute_tile(float As[STAGES][64][36], float Bs[STAGES][32][36],
                                             int buf, int m_off, int n_off, int gid, int tig,
                                             float acc[2][4])
{
    #pragma unroll
    for (int kk = 0; kk < 32; kk += 8) {
        unsigned a0 = __float_as_uint(As[buf][m_off + gid    ][kk + tig    ]);
        unsigned a1 = __float_as_uint(As[buf][m_off + gid + 8][kk + tig    ]);
        unsigned a2 = __float_as_uint(As[buf][m_off + gid    ][kk + tig + 4]);
        unsigned a3 = __float_as_uint(As[buf][m_off + gid + 8][kk + tig + 4]);
        #pragma unroll
        for (int t = 0; t < 2; t++) {
            int n = n_off + t * 8;
            unsigned b0 = __float_as_uint(Bs[buf][n + gid][kk + tig    ]);
            unsigned b1 = __float_as_uint(Bs[buf][n + gid][kk + tig + 4]);
            mma_tf32(acc[t][0], acc[t][1], acc[t][2], acc[t][3],
                     a0, a1, a2, a3, b0, b1);
        }
    }
}

// Store 64x32 partial accumulator block into partial buffer (row stride ldc).
__device__ __forceinline__ void store_partial(float* __restrict__ P, int ldc, int col0,
                                              int m_off, int n_off, int gid, int tig,
                                              float acc[2][4])
{
    #pragma unroll
    for (int t = 0; t < 2; t++) {
        int row = m_off + gid;
        int col = col0 + n_off + t * 8 + 2 * tig;
        P[(size_t)row * ldc + col]           = acc[t][0];
        P[(size_t)row * ldc + col + 1]       = acc[t][1];
        P[(size_t)(row + 8) * ldc + col]     = acc[t][2];
        P[(size_t)(row + 8) * ldc + col + 1] = acc[t][3];
    }
}

// ---------------- fused QKV projection, split-K: grid (192, SK) ----------------
// bx [0,128): q cols; [128,160): knew; [160,192): vnew. Partials layout:
// part[s][64][6144] with col concat (q | knew | vnew).
__global__ __launch_bounds__(256) void gemm_qkv_sk(
    const float* __restrict__ x,
    const float* __restrict__ Wq, const float* __restrict__ Wk, const float* __restrict__ Wv,
    float* __restrict__ part)
{
    __shared__ float As[STAGES][64][36];
    __shared__ float Bs[STAGES][32][36];
    const int tid = threadIdx.x;
    const int bx = blockIdx.x;
    const int split = blockIdx.y;
    const float* Wm; int n0, colbase;
    if (bx < 128)      { Wm = Wq; colbase = 0;    n0 = bx * 32; }
    else if (bx < 160) { Wm = Wk; colbase = D_;   n0 = (bx - 128) * 32; }
    else               { Wm = Wv; colbase = D_ + 1024; n0 = (bx - 160) * 32; }
    const int K = D_;
    const int Ks = K / SK;              // 256
    const int koff = split * Ks;
    const int T = Ks >> 5;              // 8
    const int lane = tid & 31, warp = tid >> 5;
    const int m_off = (warp & 3) * 16, n_off = (warp >> 2) * 16;
    const int gid = lane >> 2, tig = lane & 3;
    const float* A0 = x + koff;
    const float* W0 = Wm + (size_t)n0 * K + koff;

    float acc[2][4] = {};

    load_tile(As, Bs, 0, A0, K, W0, K, tid);
    load_tile(As, Bs, 1, A0 + 32, K, W0 + 32, K, tid);

    int buf = 0;
    for (int t = 0; t < T; t++) {
        asm volatile("cp.async.wait_group 1;");
        __syncthreads();
        compute_tile(As, Bs, buf, m_off, n_off, gid, tig, acc);
        int tn = t + 2;
        if (tn < T) {
            int nb = buf + 2; if (nb >= STAGES) nb -= STAGES;
            load_tile(As, Bs, nb, A0 + tn * 32, K, W0 + tn * 32, K, tid);
        } else {
            asm volatile("cp.async.commit_group;");
        }
        buf++; if (buf == STAGES) buf = 0;
    }

    float* P = part + (size_t)split * B_ * QKV_N;
    store_partial(P, QKV_N, colbase + n0, m_off, n_off, gid, tig, acc);
}

// ---------------- Wo GEMM, split-K: grid (128, SK) ----------------
// partials layout: part[s][64][4096]
__global__ __launch_bounds__(256) void gemm_wo_sk(
    const float* __restrict__ A,      // g_attn
    const float* __restrict__ Wm,     // Wo
    float* __restrict__ part)
{
    __shared__ float As[STAGES][64][36];
    __shared__ float Bs[STAGES][32][36];
    const int tid = threadIdx.x;
    const int n0 = blockIdx.x * 32;
    const int split = blockIdx.y;
    const int K = D_;
    const int Ks = K / SK;            // 256
    const int koff = split * Ks;
    const int T = Ks >> 5;            // 8
    const int lane = tid & 31, warp = tid >> 5;
    const int m_off = (warp & 3) * 16, n_off = (warp >> 2) * 16;
    const int gid = lane >> 2, tig = lane & 3;
    const float* A0 = A + koff;
    const float* W0 = Wm + (size_t)n0 * K + koff;

    float acc[2][4] = {};

    load_tile(As, Bs, 0, A0, K, W0, K, tid);
    load_tile(As, Bs, 1, A0 + 32, K, W0 + 32, K, tid);

    int buf = 0;
    for (int t = 0; t < T; t++) {
        asm volatile("cp.async.wait_group 1;");
        __syncthreads();
        compute_tile(As, Bs, buf, m_off, n_off, gid, tig, acc);
        int tn = t + 2;
        if (tn < T) {
            int nb = buf + 2; if (nb >= STAGES) nb -= STAGES;
            load_tile(As, Bs, nb, A0 + tn * 32, K, W0 + tn * 32, K, tid);
        } else {
            asm volatile("cp.async.commit_group;");
        }
        buf++; if (buf == STAGES) buf = 0;
    }

    float* P = part + (size_t)split * B_ * D_;
    store_partial(P, D_, n0, m_off, n_off, gid, tig, acc);
}

// ---------------- gate GEMM, split-K: grid (128, SK), K=8192 ----------------
// A = concat([x, oproj]) read directly. partials layout: part[s][64][4096]
__global__ __launch_bounds__(256) void gemm_gate_sk(
    const float* __restrict__ x,
    const float* __restrict__ oproj,
    const float* __restrict__ Wm,     // gate_w [4096, 8192]
    float* __restrict__ part)
{
    __shared__ float As[STAGES][64][36];
    __shared__ float Bs[STAGES][32][36];
    const int tid = threadIdx.x;
    const int n0 = blockIdx.x * 32;
    const int split = blockIdx.y;
    const int K = 2 * D_;
    const int Ks = K / SK;            // 512
    const int koff = split * Ks;
    const int T = Ks >> 5;            // 16
    const int lane = tid & 31, warp = tid >> 5;
    const int m_off = (warp & 3) * 16, n_off = (warp >> 2) * 16;
    const int gid = lane >> 2, tig = lane & 3;
    const float* W0 = Wm + (size_t)n0 * K + koff;

    float acc[2][4] = {};

    // A-tile for global k0: x if k0 < 4096 else oproj (both row stride 4096)
    {
        int k0 = koff;
        const float* At0 = (k0 < D_) ? (x + k0) : (oproj + (k0 - D_));
        int k1 = koff + 32;
        const float* At1 = (k1 < D_) ? (x + k1) : (oproj + (k1 - D_));
        load_tile(As, Bs, 0, At0, D_, W0, K, tid);
        load_tile(As, Bs, 1, At1, D_, W0 + 32, K, tid);
    }

    int buf = 0;
    for (int t = 0; t < T; t++) {
        asm volatile("cp.async.wait_group 1;");
        __syncthreads();
        compute_tile(As, Bs, buf, m_off, n_off, gid, tig, acc);
        int tn = t + 2;
        if (tn < T) {
            int k0 = koff + tn * 32;
            const float* Atile = (k0 < D_) ? (x + k0) : (oproj + (k0 - D_));
            int nb = buf + 2; if (nb >= STAGES) nb -= STAGES;
            load_tile(As, Bs, nb, Atile, D_, W0 + tn * 32, K, tid);
        } else {
            asm volatile("cp.async.commit_group;");
        }
        buf++; if (buf == STAGES) buf = 0;
    }

    float* P = part + (size_t)split * B_ * D_;
    store_partial(P, D_, n0, m_off, n_off, gid, tig, acc);
}

// ---------------- QKV reduce + RoPE: sum SK partials, rotate q/k pairs -------------
// One thread per (row, pair): 64 * 3072 threads.
__global__ void reduce_rope_kernel(const float* __restrict__ part,
                                   float* __restrict__ q, float* __restrict__ kn,
                                   float* __restrict__ vn,
                                   const int* __restrict__ pos_p) {
    const int idx = blockIdx.x * 256 + threadIdx.x;
    const int PAIRS = QKV_N / 2;  // 3072
    if (idx >= B_ * PAIRS) return;
    const int row = idx / PAIRS;
    const int col = (idx - row * PAIRS) * 2;

    float s0 = 0.0f, s1 = 0.0f;
    #pragma unroll
    for (int s = 0; s < SK; s++) {
        const float* P = part + (size_t)s * B_ * QKV_N + (size_t)row * QKV_N + col;
        s0 += P[0];
        s1 += P[1];
    }

    if (col < D_ + 1024) {
        // q or knew: apply RoPE; pair index within head
        const int i = (col >> 1) & 63;
        const float pos = (float)(*pos_p);
        const float inv = 1.0f / powf(10000.0f, (float)(2 * i) / 128.0f);
        const float ang = pos * inv;
        float sn, cs;
        sincosf(ang, &sn, &cs);
        float r0 = s0 * cs - s1 * sn;
        float r1 = s0 * sn + s1 * cs;
        if (col < D_) {
            q[(size_t)row * D_ + col]     = r0;
            q[(size_t)row * D_ + col + 1] = r1;
        } else {
            int lc = col - D_;
            kn[(size_t)row * 1024 + lc]     = r0;
            kn[(size_t)row * 1024 + lc + 1] = r1;
        }
    } else {
        int lc = col - (D_ + 1024);
        vn[(size_t)row * 1024 + lc]     = s0;
        vn[(size_t)row * 1024 + lc + 1] = s1;
    }
}

// ---------------- Wo reduce: oproj = sum of SK partials (float4) -------------------
__global__ void reduce_wo_kernel(const float* __restrict__ part, float* __restrict__ oproj) {
    const int idx = blockIdx.x * 256 + threadIdx.x;   // float4 index
    if (idx >= B_ * D_ / 4) return;
    float4 a = ((const float4*)part)[idx];
    #pragma unroll
    for (int s = 1; s < SK; s++) {
        float4 b = ((const float4*)(part + (size_t)s * B_ * D_))[idx];
        a.x += b.x; a.y += b.y; a.z += b.z; a.w += b.w;
    }
    ((float4*)oproj)[idx] = a;
}

// ---------------- gate epilogue: out = x + sigmoid(sum + bias) * oproj -------------
__global__ void gate_epilogue_kernel(const float* __restrict__ part,
                                     const float* __restrict__ bias,
                                     const float* __restrict__ x,
                                     const float* __restrict__ oproj,
                                     float* __restrict__ out) {
    const int idx = blockIdx.x * 256 + threadIdx.x;   // float4 index
    if (idx >= B_ * D_ / 4) return;
    float4 z = ((const float4*)part)[idx];
    #pragma unroll
    for (int s = 1; s < SK; s++) {
        float4 b = ((const float4*)(part + (size_t)s * B_ * D_))[idx];
        z.x += b.x; z.y += b.y; z.z += b.z; z.w += b.w;
    }
    const int col = (idx * 4) & (D_ - 1);
    float4 bi = *(const float4*)(bias + col);
    float4 xv = ((const float4*)x)[idx];
    float4 op = ((const float4*)oproj)[idx];
    float4 o;
    o.x = xv.x + op.x / (1.0f + __expf(-(z.x + bi.x)));
    o.y = xv.y + op.y / (1.0f + __expf(-(z.y + bi.y)));
    o.z = xv.z + op.z / (1.0f + __expf(-(z.z + bi.z)));
    o.w = xv.w + op.w / (1.0f + __expf(-(z.w + bi.w)));
    ((float4*)out)[idx] = o;
}

// ---------------- attention: one block per (hkv, b); 256 threads (8 warps) ---------
// Effective keys: w=0..2046 -> cache slot w+1 (drop oldest); w=2047 -> k_new/v_new.
// 4 key/value rows in flight per warp for memory-latency hiding.
__global__ void attn_kernel(const float* __restrict__ q,
                            const float* __restrict__ knew,
                            const float* __restrict__ vnew,
                            const float* __restrict__ kc,
                            const float* __restrict__ vc,
                            float* __restrict__ out) {
    const int hkv = blockIdx.x, b = blockIdx.y;
    __shared__ float s[G_][W_];        // 32 KB scores/probs
    __shared__ float red[G_][64];
    __shared__ float o_acc[G_][DH_];
    __shared__ float sm[G_];
    const int tid = threadIdx.x;
    const int lane = tid & 31, warp = tid >> 5;

    for (int i = tid; i < G_ * DH_; i += 256) ((float*)o_acc)[i] = 0.0f;

    float qr[G_][4];
    const float* qbase = q + (size_t)b * D_ + (size_t)hkv * G_ * DH_;
    #pragma unroll
    for (int g = 0; g < G_; g++) {
        float4 t = *(const float4*)(qbase + g * DH_ + lane * 4);
        qr[g][0] = t.x; qr[g][1] = t.y; qr[g][2] = t.z; qr[g][3] = t.w;
    }
    const float scale = 0.08838834764831845f;  // 128^-0.5
    const size_t cbase = ((size_t)b * HKV_ + hkv) * W_ * DH_;
    const float* knew_r = knew + ((size_t)b * HKV_ + hkv) * DH_;
    const float* vnew_r = vnew + ((size_t)b * HKV_ + hkv) * DH_;

    __syncthreads();

    // ---- pass 1: scores (4 rows in flight per warp) ----
    for (int w = warp; w < W_; w += 32) {
        float4 kv[4];
        #pragma unroll
        for (int r = 0; r < 4; r++) {
            int wr = w + r * 8;
            const float* krow = (wr < W_ - 1) ? (kc + cbase + (size_t)(wr + 1) * DH_) : knew_r;
            kv[r] = *(const float4*)(krow + lane * 4);
        }
        float p[4][G_];
        #pragma unroll
        for (int r = 0; r < 4; r++) {
            #pragma unroll
            for (int g = 0; g < G_; g++)
                p[r][g] = qr[g][0]*kv[r].x + qr[g][1]*kv[r].y + qr[g][2]*kv[r].z + qr[g][3]*kv[r].w;
        }
        #pragma unroll
        for (int off = 16; off; off >>= 1) {
            #pragma unroll
            for (int r = 0; r < 4; r++) {
                #pragma unroll
                for (int g = 0; g < G_; g++)
                    p[r][g] += __shfl_xor_sync(0xffffffffu, p[r][g], off);
            }
        }
        if (lane == 0) {
            #pragma unroll
            for (int r = 0; r < 4; r++) {
                int wr = w + r * 8;
                #pragma unroll
                for (int g = 0; g < G_; g++)
                    s[g][wr] = p[r][g] * scale;
            }
        }
    }
    __syncthreads();

    // ---- softmax (64 threads per head) ----
    {
        const int g = tid >> 6, t = tid & 63;
        float lm = -1e30f;
        for (int i = t; i < W_; i += 64) lm = fmaxf(lm, s[g][i]);
        red[g][t] = lm;
        __syncthreads();
        for (int st = 32; st; st >>= 1) {
            if (t < st) red[g][t] = fmaxf(red[g][t], red[g][t + st]);
            __syncthreads();
        }
        const float m = red[g][0];
        float ls = 0.0f;
        for (int i = t; i < W_; i += 64) {
            float e = __expf(s[g][i] - m);
            s[g][i] = e;
            ls += e;
        }
        __syncthreads();
        red[g][t] = ls;
        __syncthreads();
        for (int st = 32; st; st >>= 1) {
            if (t < st) red[g][t] += red[g][t + st];
            __syncthreads();
        }
        if (t == 0) sm[g] = red[g][0];
        __syncthreads();
    }

    // ---- pass 2: p @ V (4 rows in flight per warp) ----
    float acc[G_][4] = {};
    for (int w = warp; w < W_; w += 32) {
        float4 vv[4];
        #pragma unroll
        for (int r = 0; r < 4; r++) {
            int wr = w + r * 8;
            const float* vrow = (wr < W_ - 1) ? (vc + cbase + (size_t)(wr + 1) * DH_) : vnew_r;
            vv[r] = *(const float4*)(vrow + lane * 4);
        }
        #pragma unroll
        for (int r = 0; r < 4; r++) {
            int wr = w + r * 8;
            #pragma unroll
            for (int g = 0; g < G_; g++) {
                float pw = s[g][wr];
                acc[g][0] += pw * vv[r].x;
                acc[g][1] += pw * vv[r].y;
                acc[g][2] += pw * vv[r].z;
                acc[g][3] += pw * vv[r].w;
            }
        }
    }
    #pragma unroll
    for (int g = 0; g < G_; g++) {
        atomicAdd(&o_acc[g][lane * 4 + 0], acc[g][0]);
        atomicAdd(&o_acc[g][lane * 4 + 1], acc[g][1]);
        atomicAdd(&o_acc[g][lane * 4 + 2], acc[g][2]);
        atomicAdd(&o_acc[g][lane * 4 + 3], acc[g][3]);
    }
    __syncthreads();

    float* obase = out + (size_t)b * D_ + (size_t)hkv * G_ * DH_;
    for (int i = tid; i < G_ * DH_; i += 256) {
        int g = i >> 7, d = i & 127;
        obase[g * DH_ + d] = o_acc[g][d] / sm[g];
    }
}

// ---------------- launch ----------------
extern "C" void kernel_launch(void* const* d_in, const int* in_sizes, int n_in,
                              void* d_out, int out_size) {
    const float* x   = (const float*)d_in[0];
    const float* kc  = (const float*)d_in[1];
    const float* vc  = (const float*)d_in[2];
    const float* Wq  = (const float*)d_in[3];
    const float* Wk  = (const float*)d_in[4];
    const float* Wv  = (const float*)d_in[5];
    const float* Wo  = (const float*)d_in[6];
    const float* gw  = (const float*)d_in[7];
    const float* gb  = (const float*)d_in[8];
    const int*   pos = (const int*)d_in[9];
    float* out = (float*)d_out;

    float *qb, *knb, *vnb, *attnb, *opb, *partb;
    cudaGetSymbolAddress((void**)&qb,    g_q);
    cudaGetSymbolAddress((void**)&knb,   g_knew);
    cudaGetSymbolAddress((void**)&vnb,   g_vnew);
    cudaGetSymbolAddress((void**)&attnb, g_attn);
    cudaGetSymbolAddress((void**)&opb,   g_oproj);
    cudaGetSymbolAddress((void**)&partb, g_part);

    // QKV projections, split-K x16 -> partials
    gemm_qkv_sk<<<dim3(192, SK), 256>>>(x, Wq, Wk, Wv, partb);

    // Reduce partials + RoPE
    {
        int total = B_ * (QKV_N / 2);   // 196608 pair-threads
        reduce_rope_kernel<<<(total + 255) / 256, 256>>>(partb, qb, knb, vnb, pos);
    }

    // Attention
    attn_kernel<<<dim3(HKV_, B_), 256>>>(qb, knb, vnb, kc, vc, attnb);

    // o_proj = attn @ Wo^T  (split-K x16 -> partials -> reduce)
    gemm_wo_sk<<<dim3(128, SK), 256>>>(attnb, Wo, partb);
    reduce_wo_kernel<<<(B_ * D_ / 4 + 255) / 256, 256>>>(partb, opb);

    // Gate GEMM, split-K x16 -> partials -> fused sigmoid/residual epilogue
    gemm_gate_sk<<<dim3(128, SK), 256>>>(x, opb, gw, partb);
    gate_epilogue_kernel<<<(B_ * D_ / 4 + 255) / 256, 256>>>(partb, gb, x, opb, out);
}

// round 13
// speedup vs baseline: 1.5259x; 1.5259x over previous
#include <cuda_runtime.h>
#include <math.h>

#define B_   64
#define D_   4096
#define HKV_ 8
#define G_   4
#define DH_  128
#define W_   2048
#define STAGES 3
#define SK   8                     // split-K factor (16 regressed: pipeline fill unamortized)
#define QKV_N (D_ + 2 * HKV_ * DH_)   // 6144 concat output cols (q | knew | vnew)

// ---------------- scratch (device globals; no allocations allowed) ----------------
__device__ float g_q    [B_ * D_];             // q (RoPE'd)
__device__ float g_knew [B_ * HKV_ * DH_];     // new k (RoPE'd)
__device__ float g_vnew [B_ * HKV_ * DH_];     // new v
__device__ float g_attn [B_ * D_];             // attention output
__device__ float g_oproj[B_ * D_];             // attn @ Wo^T
__device__ float g_part [SK * B_ * QKV_N];     // split-K partials (reused by all GEMMs)

// ================= tf32 tensor-core GEMM machinery ============
// 256 threads (8 warps), block tile 64(M) x 32(N), k-tile 32, 3-stage cp.async.
// warp grid: 4 (M) x 2 (N); warp tile 16x16 = 2x mma.m16n8k8.
// fp32 bits are fed RAW to the tf32 MMA (HW ignores mantissa[12:0]) — no cvt.

__device__ __forceinline__ void mma_tf32(float& c0, float& c1, float& c2, float& c3,
                                         unsigned a0, unsigned a1, unsigned a2, unsigned a3,
                                         unsigned b0, unsigned b1) {
    asm volatile("mma.sync.aligned.m16n8k8.row.col.f32.tf32.tf32.f32 "
                 "{%0,%1,%2,%3}, {%4,%5,%6,%7}, {%8,%9}, {%0,%1,%2,%3};"
                 : "+f"(c0), "+f"(c1), "+f"(c2), "+f"(c3)
                 : "r"(a0), "r"(a1), "r"(a2), "r"(a3), "r"(b0), "r"(b1));
}

#define CP16(dst_smem_u32, src_ptr) \
    asm volatile("cp.async.cg.shared.global [%0], [%1], 16;" :: "r"(dst_smem_u32), "l"(src_ptr))

__device__ __forceinline__ void load_tile(float As[STAGES][64][36], float Bs[STAGES][32][36],
                                          int buf,
                                          const float* __restrict__ Atile, int lda,
                                          const float* __restrict__ Wtile, int ldw, int tid)
{
    #pragma unroll
    for (int j = 0; j < 2; j++) {
        int f = tid + j * 256;
        int row = f >> 3, c4 = f & 7;
        unsigned dst = (unsigned)__cvta_generic_to_shared(&As[buf][row][c4 * 4]);
        CP16(dst, Atile + (size_t)row * lda + c4 * 4);
    }
    {
        int row = tid >> 3, c4 = tid & 7;
        unsigned dst = (unsigned)__cvta_generic_to_shared(&Bs[buf][row][c4 * 4]);
        CP16(dst, Wtile + (size_t)row * ldw + c4 * 4);
    }
    asm volatile("cp.async.commit_group;");
}

__device__ __forceinline__ void compute_tile(float As[STAGES][64][36], float Bs[STAGES][32][36],
                                             int buf, int m_off, int n_off, int gid, int tig,
                                             float acc[2][4])
{
    #pragma unroll
    for (int kk = 0; kk < 32; kk += 8) {
        unsigned a0 = __float_as_uint(As[buf][m_off + gid    ][kk + tig    ]);
        unsigned a1 = __float_as_uint(As[buf][m_off + gid + 8][kk + tig    ]);
        unsigned a2 = __float_as_uint(As[buf][m_off + gid    ][kk + tig + 4]);
        unsigned a3 = __float_as_uint(As[buf][m_off + gid + 8][kk + tig + 4]);
        #pragma unroll
        for (int t = 0; t < 2; t++) {
            int n = n_off + t * 8;
            unsigned b0 = __float_as_uint(Bs[buf][n + gid][kk + tig    ]);
            unsigned b1 = __float_as_uint(Bs[buf][n + gid][kk + tig + 4]);
            mma_tf32(acc[t][0], acc[t][1], acc[t][2], acc[t][3],
                     a0, a1, a2, a3, b0, b1);
        }
    }
}

// Store 64x32 partial accumulator block into partial buffer (row stride ldc).
__device__ __forceinline__ void store_partial(float* __restrict__ P, int ldc, int col0,
                                              int m_off, int n_off, int gid, int tig,
                                              float acc[2][4])
{
    #pragma unroll
    for (int t = 0; t < 2; t++) {
        int row = m_off + gid;
        int col = col0 + n_off + t * 8 + 2 * tig;
        P[(size_t)row * ldc + col]           = acc[t][0];
        P[(size_t)row * ldc + col + 1]       = acc[t][1];
        P[(size_t)(row + 8) * ldc + col]     = acc[t][2];
        P[(size_t)(row + 8) * ldc + col + 1] = acc[t][3];
    }
}

// ---------------- fused QKV projection, split-K: grid (192, SK) ----------------
// bx [0,128): q cols; [128,160): knew; [160,192): vnew. Partials layout:
// part[s][64][6144] with col concat (q | knew | vnew).
__global__ __launch_bounds__(256) void gemm_qkv_sk(
    const float* __restrict__ x,
    const float* __restrict__ Wq, const float* __restrict__ Wk, const float* __restrict__ Wv,
    float* __restrict__ part)
{
    __shared__ float As[STAGES][64][36];
    __shared__ float Bs[STAGES][32][36];
    const int tid = threadIdx.x;
    const int bx = blockIdx.x;
    const int split = blockIdx.y;
    const float* Wm; int n0, colbase;
    if (bx < 128)      { Wm = Wq; colbase = 0;    n0 = bx * 32; }
    else if (bx < 160) { Wm = Wk; colbase = D_;   n0 = (bx - 128) * 32; }
    else               { Wm = Wv; colbase = D_ + 1024; n0 = (bx - 160) * 32; }
    const int K = D_;
    const int Ks = K / SK;              // 512
    const int koff = split * Ks;
    const int T = Ks >> 5;              // 16
    const int lane = tid & 31, warp = tid >> 5;
    const int m_off = (warp & 3) * 16, n_off = (warp >> 2) * 16;
    const int gid = lane >> 2, tig = lane & 3;
    const float* A0 = x + koff;
    const float* W0 = Wm + (size_t)n0 * K + koff;

    float acc[2][4] = {};

    load_tile(As, Bs, 0, A0, K, W0, K, tid);
    load_tile(As, Bs, 1, A0 + 32, K, W0 + 32, K, tid);

    int buf = 0;
    for (int t = 0; t < T; t++) {
        asm volatile("cp.async.wait_group 1;");
        __syncthreads();
        compute_tile(As, Bs, buf, m_off, n_off, gid, tig, acc);
        int tn = t + 2;
        if (tn < T) {
            int nb = buf + 2; if (nb >= STAGES) nb -= STAGES;
            load_tile(As, Bs, nb, A0 + tn * 32, K, W0 + tn * 32, K, tid);
        } else {
            asm volatile("cp.async.commit_group;");
        }
        buf++; if (buf == STAGES) buf = 0;
    }

    float* P = part + (size_t)split * B_ * QKV_N;
    store_partial(P, QKV_N, colbase + n0, m_off, n_off, gid, tig, acc);
}

// ---------------- Wo GEMM, split-K: grid (128, SK) ----------------
// partials layout: part[s][64][4096]
__global__ __launch_bounds__(256) void gemm_wo_sk(
    const float* __restrict__ A,      // g_attn
    const float* __restrict__ Wm,     // Wo
    float* __restrict__ part)
{
    __shared__ float As[STAGES][64][36];
    __shared__ float Bs[STAGES][32][36];
    const int tid = threadIdx.x;
    const int n0 = blockIdx.x * 32;
    const int split = blockIdx.y;
    const int K = D_;
    const int Ks = K / SK;            // 512
    const int koff = split * Ks;
    const int T = Ks >> 5;            // 16
    const int lane = tid & 31, warp = tid >> 5;
    const int m_off = (warp & 3) * 16, n_off = (warp >> 2) * 16;
    const int gid = lane >> 2, tig = lane & 3;
    const float* A0 = A + koff;
    const float* W0 = Wm + (size_t)n0 * K + koff;

    float acc[2][4] = {};

    load_tile(As, Bs, 0, A0, K, W0, K, tid);
    load_tile(As, Bs, 1, A0 + 32, K, W0 + 32, K, tid);

    int buf = 0;
    for (int t = 0; t < T; t++) {
        asm volatile("cp.async.wait_group 1;");
        __syncthreads();
        compute_tile(As, Bs, buf, m_off, n_off, gid, tig, acc);
        int tn = t + 2;
        if (tn < T) {
            int nb = buf + 2; if (nb >= STAGES) nb -= STAGES;
            load_tile(As, Bs, nb, A0 + tn * 32, K, W0 + tn * 32, K, tid);
        } else {
            asm volatile("cp.async.commit_group;");
        }
        buf++; if (buf == STAGES) buf = 0;
    }

    float* P = part + (size_t)split * B_ * D_;
    store_partial(P, D_, n0, m_off, n_off, gid, tig, acc);
}

// ---------------- gate GEMM, split-K: grid (128, SK), K=8192 ----------------
// A = concat([x, oproj]) read directly. partials layout: part[s][64][4096]
__global__ __launch_bounds__(256) void gemm_gate_sk(
    const float* __restrict__ x,
    const float* __restrict__ oproj,
    const float* __restrict__ Wm,     // gate_w [4096, 8192]
    float* __restrict__ part)
{
    __shared__ float As[STAGES][64][36];
    __shared__ float Bs[STAGES][32][36];
    const int tid = threadIdx.x;
    const int n0 = blockIdx.x * 32;
    const int split = blockIdx.y;
    const int K = 2 * D_;
    const int Ks = K / SK;            // 1024
    const int koff = split * Ks;
    const int T = Ks >> 5;            // 32
    const int lane = tid & 31, warp = tid >> 5;
    const int m_off = (warp & 3) * 16, n_off = (warp >> 2) * 16;
    const int gid = lane >> 2, tig = lane & 3;
    const float* W0 = Wm + (size_t)n0 * K + koff;

    float acc[2][4] = {};

    // A-tile for global k0: x if k0 < 4096 else oproj (both row stride 4096)
    {
        int k0 = koff;
        const float* At0 = (k0 < D_) ? (x + k0) : (oproj + (k0 - D_));
        int k1 = koff + 32;
        const float* At1 = (k1 < D_) ? (x + k1) : (oproj + (k1 - D_));
        load_tile(As, Bs, 0, At0, D_, W0, K, tid);
        load_tile(As, Bs, 1, At1, D_, W0 + 32, K, tid);
    }

    int buf = 0;
    for (int t = 0; t < T; t++) {
        asm volatile("cp.async.wait_group 1;");
        __syncthreads();
        compute_tile(As, Bs, buf, m_off, n_off, gid, tig, acc);
        int tn = t + 2;
        if (tn < T) {
            int k0 = koff + tn * 32;
            const float* Atile = (k0 < D_) ? (x + k0) : (oproj + (k0 - D_));
            int nb = buf + 2; if (nb >= STAGES) nb -= STAGES;
            load_tile(As, Bs, nb, Atile, D_, W0 + tn * 32, K, tid);
        } else {
            asm volatile("cp.async.commit_group;");
        }
        buf++; if (buf == STAGES) buf = 0;
    }

    float* P = part + (size_t)split * B_ * D_;
    store_partial(P, D_, n0, m_off, n_off, gid, tig, acc);
}

// ---------------- QKV reduce + RoPE: sum SK partials, rotate q/k pairs -------------
// One thread per (row, pair): 64 * 3072 threads.
__global__ void reduce_rope_kernel(const float* __restrict__ part,
                                   float* __restrict__ q, float* __restrict__ kn,
                                   float* __restrict__ vn,
                                   const int* __restrict__ pos_p) {
    const int idx = blockIdx.x * 256 + threadIdx.x;
    const int PAIRS = QKV_N / 2;  // 3072
    if (idx >= B_ * PAIRS) return;
    const int row = idx / PAIRS;
    const int col = (idx - row * PAIRS) * 2;

    float s0 = 0.0f, s1 = 0.0f;
    #pragma unroll
    for (int s = 0; s < SK; s++) {
        const float* P = part + (size_t)s * B_ * QKV_N + (size_t)row * QKV_N + col;
        s0 += P[0];
        s1 += P[1];
    }

    if (col < D_ + 1024) {
        // q or knew: apply RoPE; pair index within head
        const int i = (col >> 1) & 63;
        const float pos = (float)(*pos_p);
        const float inv = 1.0f / powf(10000.0f, (float)(2 * i) / 128.0f);
        const float ang = pos * inv;
        float sn, cs;
        sincosf(ang, &sn, &cs);
        float r0 = s0 * cs - s1 * sn;
        float r1 = s0 * sn + s1 * cs;
        if (col < D_) {
            q[(size_t)row * D_ + col]     = r0;
            q[(size_t)row * D_ + col + 1] = r1;
        } else {
            int lc = col - D_;
            kn[(size_t)row * 1024 + lc]     = r0;
            kn[(size_t)row * 1024 + lc + 1] = r1;
        }
    } else {
        int lc = col - (D_ + 1024);
        vn[(size_t)row * 1024 + lc]     = s0;
        vn[(size_t)row * 1024 + lc + 1] = s1;
    }
}

// ---------------- Wo reduce: oproj = sum of SK partials (float4) -------------------
__global__ void reduce_wo_kernel(const float* __restrict__ part, float* __restrict__ oproj) {
    const int idx = blockIdx.x * 256 + threadIdx.x;   // float4 index
    if (idx >= B_ * D_ / 4) return;
    float4 a = ((const float4*)part)[idx];
    #pragma unroll
    for (int s = 1; s < SK; s++) {
        float4 b = ((const float4*)(part + (size_t)s * B_ * D_))[idx];
        a.x += b.x; a.y += b.y; a.z += b.z; a.w += b.w;
    }
    ((float4*)oproj)[idx] = a;
}

// ---------------- gate epilogue: out = x + sigmoid(sum + bias) * oproj -------------
__global__ void gate_epilogue_kernel(const float* __restrict__ part,
                                     const float* __restrict__ bias,
                                     const float* __restrict__ x,
                                     const float* __restrict__ oproj,
                                     float* __restrict__ out) {
    const int idx = blockIdx.x * 256 + threadIdx.x;   // float4 index
    if (idx >= B_ * D_ / 4) return;
    float4 z = ((const float4*)part)[idx];
    #pragma unroll
    for (int s = 1; s < SK; s++) {
        float4 b = ((const float4*)(part + (size_t)s * B_ * D_))[idx];
        z.x += b.x; z.y += b.y; z.z += b.z; z.w += b.w;
    }
    const int col = (idx * 4) & (D_ - 1);
    float4 bi = *(const float4*)(bias + col);
    float4 xv = ((const float4*)x)[idx];
    float4 op = ((const float4*)oproj)[idx];
    float4 o;
    o.x = xv.x + op.x / (1.0f + __expf(-(z.x + bi.x)));
    o.y = xv.y + op.y / (1.0f + __expf(-(z.y + bi.y)));
    o.z = xv.z + op.z / (1.0f + __expf(-(z.z + bi.z)));
    o.w = xv.w + op.w / (1.0f + __expf(-(z.w + bi.w)));
    ((float4*)out)[idx] = o;
}

// ---------------- attention: one block per (hkv, b); 256 threads (8 warps) ---------
// Effective keys: w=0..2046 -> cache slot w+1 (drop oldest); w=2047 -> k_new/v_new.
// 4 key/value rows in flight per warp for memory-latency hiding.
__global__ void attn_kernel(const float* __restrict__ q,
                            const float* __restrict__ knew,
                            const float* __restrict__ vnew,
                            const float* __restrict__ kc,
                            const float* __restrict__ vc,
                            float* __restrict__ out) {
    const int hkv = blockIdx.x, b = blockIdx.y;
    __shared__ float s[G_][W_];        // 32 KB scores/probs
    __shared__ float red[G_][64];
    __shared__ float o_acc[G_][DH_];
    __shared__ float sm[G_];
    const int tid = threadIdx.x;
    const int lane = tid & 31, warp = tid >> 5;

    for (int i = tid; i < G_ * DH_; i += 256) ((float*)o_acc)[i] = 0.0f;

    float qr[G_][4];
    const float* qbase = q + (size_t)b * D_ + (size_t)hkv * G_ * DH_;
    #pragma unroll
    for (int g = 0; g < G_; g++) {
        float4 t = *(const float4*)(qbase + g * DH_ + lane * 4);
        qr[g][0] = t.x; qr[g][1] = t.y; qr[g][2] = t.z; qr[g][3] = t.w;
    }
    const float scale = 0.08838834764831845f;  // 128^-0.5
    const size_t cbase = ((size_t)b * HKV_ + hkv) * W_ * DH_;
    const float* knew_r = knew + ((size_t)b * HKV_ + hkv) * DH_;
    const float* vnew_r = vnew + ((size_t)b * HKV_ + hkv) * DH_;

    __syncthreads();

    // ---- pass 1: scores (4 rows in flight per warp) ----
    for (int w = warp; w < W_; w += 32) {
        float4 kv[4];
        #pragma unroll
        for (int r = 0; r < 4; r++) {
            int wr = w + r * 8;
            const float* krow = (wr < W_ - 1) ? (kc + cbase + (size_t)(wr + 1) * DH_) : knew_r;
            kv[r] = *(const float4*)(krow + lane * 4);
        }
        float p[4][G_];
        #pragma unroll
        for (int r = 0; r < 4; r++) {
            #pragma unroll
            for (int g = 0; g < G_; g++)
                p[r][g] = qr[g][0]*kv[r].x + qr[g][1]*kv[r].y + qr[g][2]*kv[r].z + qr[g][3]*kv[r].w;
        }
        #pragma unroll
        for (int off = 16; off; off >>= 1) {
            #pragma unroll
            for (int r = 0; r < 4; r++) {
                #pragma unroll
                for (int g = 0; g < G_; g++)
                    p[r][g] += __shfl_xor_sync(0xffffffffu, p[r][g], off);
            }
        }
        if (lane == 0) {
            #pragma unroll
            for (int r = 0; r < 4; r++) {
                int wr = w + r * 8;
                #pragma unroll
                for (int g = 0; g < G_; g++)
                    s[g][wr] = p[r][g] * scale;
            }
        }
    }
    __syncthreads();

    // ---- softmax (64 threads per head) ----
    {
        const int g = tid >> 6, t = tid & 63;
        float lm = -1e30f;
        for (int i = t; i < W_; i += 64) lm = fmaxf(lm, s[g][i]);
        red[g][t] = lm;
        __syncthreads();
        for (int st = 32; st; st >>= 1) {
            if (t < st) red[g][t] = fmaxf(red[g][t], red[g][t + st]);
            __syncthreads();
        }
        const float m = red[g][0];
        float ls = 0.0f;
        for (int i = t; i < W_; i += 64) {
            float e = __expf(s[g][i] - m);
            s[g][i] = e;
            ls += e;
        }
        __syncthreads();
        red[g][t] = ls;
        __syncthreads();
        for (int st = 32; st; st >>= 1) {
            if (t < st) red[g][t] += red[g][t + st];
            __syncthreads();
        }
        if (t == 0) sm[g] = red[g][0];
        __syncthreads();
    }

    // ---- pass 2: p @ V (4 rows in flight per warp) ----
    float acc[G_][4] = {};
    for (int w = warp; w < W_; w += 32) {
        float4 vv[4];
        #pragma unroll
        for (int r = 0; r < 4; r++) {
            int wr = w + r * 8;
            const float* vrow = (wr < W_ - 1) ? (vc + cbase + (size_t)(wr + 1) * DH_) : vnew_r;
            vv[r] = *(const float4*)(vrow + lane * 4);
        }
        #pragma unroll
        for (int r = 0; r < 4; r++) {
            int wr = w + r * 8;
            #pragma unroll
            for (int g = 0; g < G_; g++) {
                float pw = s[g][wr];
                acc[g][0] += pw * vv[r].x;
                acc[g][1] += pw * vv[r].y;
                acc[g][2] += pw * vv[r].z;
                acc[g][3] += pw * vv[r].w;
            }
        }
    }
    #pragma unroll
    for (int g = 0; g < G_; g++) {
        atomicAdd(&o_acc[g][lane * 4 + 0], acc[g][0]);
        atomicAdd(&o_acc[g][lane * 4 + 1], acc[g][1]);
        atomicAdd(&o_acc[g][lane * 4 + 2], acc[g][2]);
        atomicAdd(&o_acc[g][lane * 4 + 3], acc[g][3]);
    }
    __syncthreads();

    float* obase = out + (size_t)b * D_ + (size_t)hkv * G_ * DH_;
    for (int i = tid; i < G_ * DH_; i += 256) {
        int g = i >> 7, d = i & 127;
        obase[g * DH_ + d] = o_acc[g][d] / sm[g];
    }
}

// ---------------- launch ----------------
extern "C" void kernel_launch(void* const* d_in, const int* in_sizes, int n_in,
                              void* d_out, int out_size) {
    const float* x   = (const float*)d_in[0];
    const float* kc  = (const float*)d_in[1];
    const float* vc  = (const float*)d_in[2];
    const float* Wq  = (const float*)d_in[3];
    const float* Wk  = (const float*)d_in[4];
    const float* Wv  = (const float*)d_in[5];
    const float* Wo  = (const float*)d_in[6];
    const float* gw  = (const float*)d_in[7];
    const float* gb  = (const float*)d_in[8];
    const int*   pos = (const int*)d_in[9];
    float* out = (float*)d_out;

    float *qb, *knb, *vnb, *attnb, *opb, *partb;
    cudaGetSymbolAddress((void**)&qb,    g_q);
    cudaGetSymbolAddress((void**)&knb,   g_knew);
    cudaGetSymbolAddress((void**)&vnb,   g_vnew);
    cudaGetSymbolAddress((void**)&attnb, g_attn);
    cudaGetSymbolAddress((void**)&opb,   g_oproj);
    cudaGetSymbolAddress((void**)&partb, g_part);

    // QKV projections, split-K x8 -> partials
    gemm_qkv_sk<<<dim3(192, SK), 256>>>(x, Wq, Wk, Wv, partb);

    // Reduce partials + RoPE
    {
        int total = B_ * (QKV_N / 2);   // 196608 pair-threads
        reduce_rope_kernel<<<(total + 255) / 256, 256>>>(partb, qb, knb, vnb, pos);
    }

    // Attention
    attn_kernel<<<dim3(HKV_, B_), 256>>>(qb, knb, vnb, kc, vc, attnb);

    // o_proj = attn @ Wo^T  (split-K x8 -> partials -> reduce)
    gemm_wo_sk<<<dim3(128, SK), 256>>>(attnb, Wo, partb);
    reduce_wo_kernel<<<(B_ * D_ / 4 + 255) / 256, 256>>>(partb, opb);

    // Gate GEMM, split-K x8 -> partials -> fused sigmoid/residual epilogue
    gemm_gate_sk<<<dim3(128, SK), 256>>>(x, opb, gw, partb);
    gate_epilogue_kernel<<<(B_ * D_ / 4 + 255) / 256, 256>>>(partb, gb, x, opb, out);
}

// round 14
// speedup vs baseline: 1.5764x; 1.0331x over previous
#include <cuda_runtime.h>
#include <math.h>

#define B_   64
#define D_   4096
#define HKV_ 8
#define G_   4
#define DH_  128
#define W_   2048
#define STAGES 4
#define SK   4                     // split-K (grid 512 = single wave at 4 CTAs/SM)
#define QKV_N (D_ + 2 * HKV_ * DH_)   // 6144 concat output cols (q | knew | vnew)

// ---------------- scratch (device globals; no allocations allowed) ----------------
__device__ float g_q    [B_ * D_];             // q (RoPE'd)
__device__ float g_knew [B_ * HKV_ * DH_];     // new k (RoPE'd)
__device__ float g_vnew [B_ * HKV_ * DH_];     // new v
__device__ float g_attn [B_ * D_];             // attention output
__device__ float g_oproj[B_ * D_];             // attn @ Wo^T
__device__ float g_part [SK * B_ * QKV_N];     // split-K partials (reused by all GEMMs)

// ================= tf32 tensor-core GEMM machinery ============
// 256 threads (8 warps), block tile 64(M) x 32(N), k-tile 32, 4-stage cp.async
// (wait_group 2 -> 3 tile-groups = 36 KB in flight per CTA).
// Smem tiles are XOR-swizzled (float4 group c4 ^= row&7), unpadded: exactly 48 KB
// static -> 4 CTAs/SM. Reads are bank-conflict-free: bank = 4*(g^gid)+tig.
// fp32 bits are fed RAW to the tf32 MMA (HW ignores mantissa[12:0]) — no cvt.

__device__ __forceinline__ void mma_tf32(float& c0, float& c1, float& c2, float& c3,
                                         unsigned a0, unsigned a1, unsigned a2, unsigned a3,
                                         unsigned b0, unsigned b1) {
    asm volatile("mma.sync.aligned.m16n8k8.row.col.f32.tf32.tf32.f32 "
                 "{%0,%1,%2,%3}, {%4,%5,%6,%7}, {%8,%9}, {%0,%1,%2,%3};"
                 : "+f"(c0), "+f"(c1), "+f"(c2), "+f"(c3)
                 : "r"(a0), "r"(a1), "r"(a2), "r"(a3), "r"(b0), "r"(b1));
}

#define CP16(dst_smem_u32, src_ptr) \
    asm volatile("cp.async.cg.shared.global [%0], [%1], 16;" :: "r"(dst_smem_u32), "l"(src_ptr))

// Load one 64x32 A tile + 32x32 W tile into swizzled smem stage `buf`, commit group.
__device__ __forceinline__ void load_tile(float As[STAGES][64][32], float Bs[STAGES][32][32],
                                          int buf,
                                          const float* __restrict__ Atile, int lda,
                                          const float* __restrict__ Wtile, int ldw, int tid)
{
    #pragma unroll
    for (int j = 0; j < 2; j++) {
        int f = tid + j * 256;
        int row = f >> 3, c4 = f & 7;
        int c4s = c4 ^ (row & 7);
        unsigned dst = (unsigned)__cvta_generic_to_shared(&As[buf][row][c4s * 4]);
        CP16(dst, Atile + (size_t)row * lda + c4 * 4);
    }
    {
        int row = tid >> 3, c4 = tid & 7;
        int c4s = c4 ^ (row & 7);
        unsigned dst = (unsigned)__cvta_generic_to_shared(&Bs[buf][row][c4s * 4]);
        CP16(dst, Wtile + (size_t)row * ldw + c4 * 4);
    }
    asm volatile("cp.async.commit_group;");
}

// Core compute for one resident (swizzled) k-tile.
// Logical col kk+tig lives at float offset ((g ^ (row&7))<<2)+tig, g = (kk+tig)>>2.
// kk = 8s => groups g0=2s (cols kk..kk+3) and g1=2s+1 (cols kk+4..kk+7).
// All fragment rows satisfy row&7 == gid, so the XOR term is (g ^ gid).
__device__ __forceinline__ void compute_tile(float As[STAGES][64][32], float Bs[STAGES][32][32],
                                             int buf, int m_off, int n_off, int gid, int tig,
                                             float acc[2][4])
{
    #pragma unroll
    for (int s = 0; s < 4; s++) {
        const int g0 = 2 * s, g1 = 2 * s + 1;
        const int off0 = ((g0 ^ gid) << 2) + tig;
        const int off1 = ((g1 ^ gid) << 2) + tig;
        unsigned a0 = __float_as_uint(As[buf][m_off + gid    ][off0]);
        unsigned a1 = __float_as_uint(As[buf][m_off + gid + 8][off0]);
        unsigned a2 = __float_as_uint(As[buf][m_off + gid    ][off1]);
        unsigned a3 = __float_as_uint(As[buf][m_off + gid + 8][off1]);
        #pragma unroll
        for (int t = 0; t < 2; t++) {
            int n = n_off + t * 8;
            unsigned b0 = __float_as_uint(Bs[buf][n + gid][off0]);
            unsigned b1 = __float_as_uint(Bs[buf][n + gid][off1]);
            mma_tf32(acc[t][0], acc[t][1], acc[t][2], acc[t][3],
                     a0, a1, a2, a3, b0, b1);
        }
    }
}

// Store 64x32 partial accumulator block into partial buffer (row stride ldc).
__device__ __forceinline__ void store_partial(float* __restrict__ P, int ldc, int col0,
                                              int m_off, int n_off, int gid, int tig,
                                              float acc[2][4])
{
    #pragma unroll
    for (int t = 0; t < 2; t++) {
        int row = m_off + gid;
        int col = col0 + n_off + t * 8 + 2 * tig;
        P[(size_t)row * ldc + col]           = acc[t][0];
        P[(size_t)row * ldc + col + 1]       = acc[t][1];
        P[(size_t)(row + 8) * ldc + col]     = acc[t][2];
        P[(size_t)(row + 8) * ldc + col + 1] = acc[t][3];
    }
}

// Shared pipelined mainloop: T k-tiles starting with 3 preloaded stages.
#define GEMM_PIPELINE(T, LOAD_STMT)                                        \
    int buf = 0;                                                           \
    for (int t = 0; t < (T); t++) {                                        \
        asm volatile("cp.async.wait_group 2;");                            \
        __syncthreads();                                                   \
        compute_tile(As, Bs, buf, m_off, n_off, gid, tig, acc);            \
        int tn = t + STAGES - 1;                                           \
        if (tn < (T)) {                                                    \
            int nb = buf + STAGES - 1; if (nb >= STAGES) nb -= STAGES;     \
            LOAD_STMT;                                                     \
        } else {                                                           \
            asm volatile("cp.async.commit_group;");                        \
        }                                                                  \
        buf++; if (buf == STAGES) buf = 0;                                 \
    }

// ---------------- fused QKV projection, split-K: grid (192, SK) ----------------
// bx [0,128): q cols; [128,160): knew; [160,192): vnew. Partials layout:
// part[s][64][6144] with col concat (q | knew | vnew).
__global__ __launch_bounds__(256) void gemm_qkv_sk(
    const float* __restrict__ x,
    const float* __restrict__ Wq, const float* __restrict__ Wk, const float* __restrict__ Wv,
    float* __restrict__ part)
{
    __shared__ float As[STAGES][64][32];
    __shared__ float Bs[STAGES][32][32];
    const int tid = threadIdx.x;
    const int bx = blockIdx.x;
    const int split = blockIdx.y;
    const float* Wm; int n0, colbase;
    if (bx < 128)      { Wm = Wq; colbase = 0;    n0 = bx * 32; }
    else if (bx < 160) { Wm = Wk; colbase = D_;   n0 = (bx - 128) * 32; }
    else               { Wm = Wv; colbase = D_ + 1024; n0 = (bx - 160) * 32; }
    const int K = D_;
    const int Ks = K / SK;              // 1024
    const int koff = split * Ks;
    const int T = Ks >> 5;              // 32
    const int lane = tid & 31, warp = tid >> 5;
    const int m_off = (warp & 3) * 16, n_off = (warp >> 2) * 16;
    const int gid = lane >> 2, tig = lane & 3;
    const float* A0 = x + koff;
    const float* W0 = Wm + (size_t)n0 * K + koff;

    float acc[2][4] = {};

    load_tile(As, Bs, 0, A0, K, W0, K, tid);
    load_tile(As, Bs, 1, A0 + 32, K, W0 + 32, K, tid);
    load_tile(As, Bs, 2, A0 + 64, K, W0 + 64, K, tid);

    GEMM_PIPELINE(T, load_tile(As, Bs, nb, A0 + tn * 32, K, W0 + tn * 32, K, tid))

    float* P = part + (size_t)split * B_ * QKV_N;
    store_partial(P, QKV_N, colbase + n0, m_off, n_off, gid, tig, acc);
}

// ---------------- Wo GEMM, split-K: grid (128, SK) ----------------
// partials layout: part[s][64][4096]
__global__ __launch_bounds__(256) void gemm_wo_sk(
    const float* __restrict__ A,      // g_attn
    const float* __restrict__ Wm,     // Wo
    float* __restrict__ part)
{
    __shared__ float As[STAGES][64][32];
    __shared__ float Bs[STAGES][32][32];
    const int tid = threadIdx.x;
    const int n0 = blockIdx.x * 32;
    const int split = blockIdx.y;
    const int K = D_;
    const int Ks = K / SK;            // 1024
    const int koff = split * Ks;
    const int T = Ks >> 5;            // 32
    const int lane = tid & 31, warp = tid >> 5;
    const int m_off = (warp & 3) * 16, n_off = (warp >> 2) * 16;
    const int gid = lane >> 2, tig = lane & 3;
    const float* A0 = A + koff;
    const float* W0 = Wm + (size_t)n0 * K + koff;

    float acc[2][4] = {};

    load_tile(As, Bs, 0, A0, K, W0, K, tid);
    load_tile(As, Bs, 1, A0 + 32, K, W0 + 32, K, tid);
    load_tile(As, Bs, 2, A0 + 64, K, W0 + 64, K, tid);

    GEMM_PIPELINE(T, load_tile(As, Bs, nb, A0 + tn * 32, K, W0 + tn * 32, K, tid))

    float* P = part + (size_t)split * B_ * D_;
    store_partial(P, D_, n0, m_off, n_off, gid, tig, acc);
}

// ---------------- gate GEMM, split-K: grid (128, SK), K=8192 ----------------
// A = concat([x, oproj]) read directly. partials layout: part[s][64][4096]
__global__ __launch_bounds__(256) void gemm_gate_sk(
    const float* __restrict__ x,
    const float* __restrict__ oproj,
    const float* __restrict__ Wm,     // gate_w [4096, 8192]
    float* __restrict__ part)
{
    __shared__ float As[STAGES][64][32];
    __shared__ float Bs[STAGES][32][32];
    const int tid = threadIdx.x;
    const int n0 = blockIdx.x * 32;
    const int split = blockIdx.y;
    const int K = 2 * D_;
    const int Ks = K / SK;            // 2048
    const int koff = split * Ks;
    const int T = Ks >> 5;            // 64
    const int lane = tid & 31, warp = tid >> 5;
    const int m_off = (warp & 3) * 16, n_off = (warp >> 2) * 16;
    const int gid = lane >> 2, tig = lane & 3;
    const float* W0 = Wm + (size_t)n0 * K + koff;

    float acc[2][4] = {};

    // A-tile for global k0: x if k0 < 4096 else oproj (both row stride 4096)
    #pragma unroll
    for (int s = 0; s < STAGES - 1; s++) {
        int k0 = koff + s * 32;
        const float* At = (k0 < D_) ? (x + k0) : (oproj + (k0 - D_));
        load_tile(As, Bs, s, At, D_, W0 + s * 32, K, tid);
    }

    GEMM_PIPELINE(T,
        {
            int k0 = koff + tn * 32;
            const float* Atile = (k0 < D_) ? (x + k0) : (oproj + (k0 - D_));
            load_tile(As, Bs, nb, Atile, D_, W0 + tn * 32, K, tid);
        })

    float* P = part + (size_t)split * B_ * D_;
    store_partial(P, D_, n0, m_off, n_off, gid, tig, acc);
}

// ---------------- QKV reduce + RoPE: sum SK partials, rotate q/k pairs -------------
// One thread per (row, pair): 64 * 3072 threads.
__global__ void reduce_rope_kernel(const float* __restrict__ part,
                                   float* __restrict__ q, float* __restrict__ kn,
                                   float* __restrict__ vn,
                                   const int* __restrict__ pos_p) {
    const int idx = blockIdx.x * 256 + threadIdx.x;
    const int PAIRS = QKV_N / 2;  // 3072
    if (idx >= B_ * PAIRS) return;
    const int row = idx / PAIRS;
    const int col = (idx - row * PAIRS) * 2;

    float s0 = 0.0f, s1 = 0.0f;
    #pragma unroll
    for (int s = 0; s < SK; s++) {
        const float* P = part + (size_t)s * B_ * QKV_N + (size_t)row * QKV_N + col;
        s0 += P[0];
        s1 += P[1];
    }

    if (col < D_ + 1024) {
        // q or knew: apply RoPE; pair index within head
        const int i = (col >> 1) & 63;
        const float pos = (float)(*pos_p);
        const float inv = 1.0f / powf(10000.0f, (float)(2 * i) / 128.0f);
        const float ang = pos * inv;
        float sn, cs;
        sincosf(ang, &sn, &cs);
        float r0 = s0 * cs - s1 * sn;
        float r1 = s0 * sn + s1 * cs;
        if (col < D_) {
            q[(size_t)row * D_ + col]     = r0;
            q[(size_t)row * D_ + col + 1] = r1;
        } else {
            int lc = col - D_;
            kn[(size_t)row * 1024 + lc]     = r0;
            kn[(size_t)row * 1024 + lc + 1] = r1;
        }
    } else {
        int lc = col - (D_ + 1024);
        vn[(size_t)row * 1024 + lc]     = s0;
        vn[(size_t)row * 1024 + lc + 1] = s1;
    }
}

// ---------------- Wo reduce: oproj = sum of SK partials (float4) -------------------
__global__ void reduce_wo_kernel(const float* __restrict__ part, float* __restrict__ oproj) {
    const int idx = blockIdx.x * 256 + threadIdx.x;   // float4 index
    if (idx >= B_ * D_ / 4) return;
    float4 a = ((const float4*)part)[idx];
    #pragma unroll
    for (int s = 1; s < SK; s++) {
        float4 b = ((const float4*)(part + (size_t)s * B_ * D_))[idx];
        a.x += b.x; a.y += b.y; a.z += b.z; a.w += b.w;
    }
    ((float4*)oproj)[idx] = a;
}

// ---------------- gate epilogue: out = x + sigmoid(sum + bias) * oproj -------------
__global__ void gate_epilogue_kernel(const float* __restrict__ part,
                                     const float* __restrict__ bias,
                                     const float* __restrict__ x,
                                     const float* __restrict__ oproj,
                                     float* __restrict__ out) {
    const int idx = blockIdx.x * 256 + threadIdx.x;   // float4 index
    if (idx >= B_ * D_ / 4) return;
    float4 z = ((const float4*)part)[idx];
    #pragma unroll
    for (int s = 1; s < SK; s++) {
        float4 b = ((const float4*)(part + (size_t)s * B_ * D_))[idx];
        z.x += b.x; z.y += b.y; z.z += b.z; z.w += b.w;
    }
    const int col = (idx * 4) & (D_ - 1);
    float4 bi = *(const float4*)(bias + col);
    float4 xv = ((const float4*)x)[idx];
    float4 op = ((const float4*)oproj)[idx];
    float4 o;
    o.x = xv.x + op.x / (1.0f + __expf(-(z.x + bi.x)));
    o.y = xv.y + op.y / (1.0f + __expf(-(z.y + bi.y)));
    o.z = xv.z + op.z / (1.0f + __expf(-(z.z + bi.z)));
    o.w = xv.w + op.w / (1.0f + __expf(-(z.w + bi.w)));
    ((float4*)out)[idx] = o;
}

// ---------------- attention: one block per (hkv, b); 256 threads (8 warps) ---------
// Effective keys: w=0..2046 -> cache slot w+1 (drop oldest); w=2047 -> k_new/v_new.
// 4 key/value rows in flight per warp for memory-latency hiding.
__global__ void attn_kernel(const float* __restrict__ q,
                            const float* __restrict__ knew,
                            const float* __restrict__ vnew,
                            const float* __restrict__ kc,
                            const float* __restrict__ vc,
                            float* __restrict__ out) {
    const int hkv = blockIdx.x, b = blockIdx.y;
    __shared__ float s[G_][W_];        // 32 KB scores/probs
    __shared__ float red[G_][64];
    __shared__ float o_acc[G_][DH_];
    __shared__ float sm[G_];
    const int tid = threadIdx.x;
    const int lane = tid & 31, warp = tid >> 5;

    for (int i = tid; i < G_ * DH_; i += 256) ((float*)o_acc)[i] = 0.0f;

    float qr[G_][4];
    const float* qbase = q + (size_t)b * D_ + (size_t)hkv * G_ * DH_;
    #pragma unroll
    for (int g = 0; g < G_; g++) {
        float4 t = *(const float4*)(qbase + g * DH_ + lane * 4);
        qr[g][0] = t.x; qr[g][1] = t.y; qr[g][2] = t.z; qr[g][3] = t.w;
    }
    const float scale = 0.08838834764831845f;  // 128^-0.5
    const size_t cbase = ((size_t)b * HKV_ + hkv) * W_ * DH_;
    const float* knew_r = knew + ((size_t)b * HKV_ + hkv) * DH_;
    const float* vnew_r = vnew + ((size_t)b * HKV_ + hkv) * DH_;

    __syncthreads();

    // ---- pass 1: scores (4 rows in flight per warp) ----
    for (int w = warp; w < W_; w += 32) {
        float4 kv[4];
        #pragma unroll
        for (int r = 0; r < 4; r++) {
            int wr = w + r * 8;
            const float* krow = (wr < W_ - 1) ? (kc + cbase + (size_t)(wr + 1) * DH_) : knew_r;
            kv[r] = *(const float4*)(krow + lane * 4);
        }
        float p[4][G_];
        #pragma unroll
        for (int r = 0; r < 4; r++) {
            #pragma unroll
            for (int g = 0; g < G_; g++)
                p[r][g] = qr[g][0]*kv[r].x + qr[g][1]*kv[r].y + qr[g][2]*kv[r].z + qr[g][3]*kv[r].w;
        }
        #pragma unroll
        for (int off = 16; off; off >>= 1) {
            #pragma unroll
            for (int r = 0; r < 4; r++) {
                #pragma unroll
                for (int g = 0; g < G_; g++)
                    p[r][g] += __shfl_xor_sync(0xffffffffu, p[r][g], off);
            }
        }
        if (lane == 0) {
            #pragma unroll
            for (int r = 0; r < 4; r++) {
                int wr = w + r * 8;
                #pragma unroll
                for (int g = 0; g < G_; g++)
                    s[g][wr] = p[r][g] * scale;
            }
        }
    }
    __syncthreads();

    // ---- softmax (64 threads per head) ----
    {
        const int g = tid >> 6, t = tid & 63;
        float lm = -1e30f;
        for (int i = t; i < W_; i += 64) lm = fmaxf(lm, s[g][i]);
        red[g][t] = lm;
        __syncthreads();
        for (int st = 32; st; st >>= 1) {
            if (t < st) red[g][t] = fmaxf(red[g][t], red[g][t + st]);
            __syncthreads();
        }
        const float m = red[g][0];
        float ls = 0.0f;
        for (int i = t; i < W_; i += 64) {
            float e = __expf(s[g][i] - m);
            s[g][i] = e;
            ls += e;
        }
        __syncthreads();
        red[g][t] = ls;
        __syncthreads();
        for (int st = 32; st; st >>= 1) {
            if (t < st) red[g][t] += red[g][t + st];
            __syncthreads();
        }
        if (t == 0) sm[g] = red[g][0];
        __syncthreads();
    }

    // ---- pass 2: p @ V (4 rows in flight per warp) ----
    float acc[G_][4] = {};
    for (int w = warp; w < W_; w += 32) {
        float4 vv[4];
        #pragma unroll
        for (int r = 0; r < 4; r++) {
            int wr = w + r * 8;
            const float* vrow = (wr < W_ - 1) ? (vc + cbase + (size_t)(wr + 1) * DH_) : vnew_r;
            vv[r] = *(const float4*)(vrow + lane * 4);
        }
        #pragma unroll
        for (int r = 0; r < 4; r++) {
            int wr = w + r * 8;
            #pragma unroll
            for (int g = 0; g < G_; g++) {
                float pw = s[g][wr];
                acc[g][0] += pw * vv[r].x;
                acc[g][1] += pw * vv[r].y;
                acc[g][2] += pw * vv[r].z;
                acc[g][3] += pw * vv[r].w;
            }
        }
    }
    #pragma unroll
    for (int g = 0; g < G_; g++) {
        atomicAdd(&o_acc[g][lane * 4 + 0], acc[g][0]);
        atomicAdd(&o_acc[g][lane * 4 + 1], acc[g][1]);
        atomicAdd(&o_acc[g][lane * 4 + 2], acc[g][2]);
        atomicAdd(&o_acc[g][lane * 4 + 3], acc[g][3]);
    }
    __syncthreads();

    float* obase = out + (size_t)b * D_ + (size_t)hkv * G_ * DH_;
    for (int i = tid; i < G_ * DH_; i += 256) {
        int g = i >> 7, d = i & 127;
        obase[g * DH_ + d] = o_acc[g][d] / sm[g];
    }
}

// ---------------- launch ----------------
extern "C" void kernel_launch(void* const* d_in, const int* in_sizes, int n_in,
                              void* d_out, int out_size) {
    const float* x   = (const float*)d_in[0];
    const float* kc  = (const float*)d_in[1];
    const float* vc  = (const float*)d_in[2];
    const float* Wq  = (const float*)d_in[3];
    const float* Wk  = (const float*)d_in[4];
    const float* Wv  = (const float*)d_in[5];
    const float* Wo  = (const float*)d_in[6];
    const float* gw  = (const float*)d_in[7];
    const float* gb  = (const float*)d_in[8];
    const int*   pos = (const int*)d_in[9];
    float* out = (float*)d_out;

    float *qb, *knb, *vnb, *attnb, *opb, *partb;
    cudaGetSymbolAddress((void**)&qb,    g_q);
    cudaGetSymbolAddress((void**)&knb,   g_knew);
    cudaGetSymbolAddress((void**)&vnb,   g_vnew);
    cudaGetSymbolAddress((void**)&attnb, g_attn);
    cudaGetSymbolAddress((void**)&opb,   g_oproj);
    cudaGetSymbolAddress((void**)&partb, g_part);

    // QKV projections, split-K x4 -> partials
    gemm_qkv_sk<<<dim3(192, SK), 256>>>(x, Wq, Wk, Wv, partb);

    // Reduce partials + RoPE
    {
        int total = B_ * (QKV_N / 2);   // 196608 pair-threads
        reduce_rope_kernel<<<(total + 255) / 256, 256>>>(partb, qb, knb, vnb, pos);
    }

    // Attention
    attn_kernel<<<dim3(HKV_, B_), 256>>>(qb, knb, vnb, kc, vc, attnb);

    // o_proj = attn @ Wo^T  (split-K x4 -> partials -> reduce)
    gemm_wo_sk<<<dim3(128, SK), 256>>>(attnb, Wo, partb);
    reduce_wo_kernel<<<(B_ * D_ / 4 + 255) / 256, 256>>>(partb, opb);

    // Gate GEMM, split-K x4 -> partials -> fused sigmoid/residual epilogue
    gemm_gate_sk<<<dim3(128, SK), 256>>>(x, opb, gw, partb);
    gate_epilogue_kernel<<<(B_ * D_ / 4 + 255) / 256, 256>>>(partb, gb, x, opb, out);
}